// round 6
// baseline (speedup 1.0000x reference)
#include <cuda_runtime.h>
#include <math.h>

// ChamferLoss: B=8, N=M=4096, D=3
// d_in[0] = predicted [8,4096,3] f32, d_in[1] = target [8,4096,3] f32, out = scalar f32

#define BATCH    8
#define NPTS     4096
#define THREADS  128
#define PPT      8                    // source points per thread
#define TCHUNK   512                  // targets per block chunk (8 KB smem)
#define TGROUPS  (TCHUNK / 2)         // 256 packed 2-target groups
#define NCOMBO   16                   // 8 batches x 2 directions
#define SRCSLICES (NPTS / (THREADS * PPT))   // 4
#define TCHUNKS  (NPTS / TCHUNK)      // 8
#define NBLOCKS  (NCOMBO * SRCSLICES * TCHUNKS)   // 512
#define NMIN     (NCOMBO * NPTS)      // 65536 slots

// key = ~bits(d2). d2>=0 so bigger key <=> smaller d2; initial 0 is identity for atomicMax.
__device__ unsigned int g_keybuf[NMIN];   // zero-initialized at module load; reset each run
__device__ unsigned int g_tick = 0;

static __device__ __forceinline__ unsigned long long pk2(float lo, float hi) {
    unsigned long long r;
    asm("mov.b64 %0, {%1, %2};" : "=l"(r) : "f"(lo), "f"(hi));
    return r;
}
static __device__ __forceinline__ unsigned long long fma2(unsigned long long a,
                                                          unsigned long long b,
                                                          unsigned long long c) {
    unsigned long long d;
    asm("fma.rn.f32x2 %0, %1, %2, %3;" : "=l"(d) : "l"(a), "l"(b), "l"(c));
    return d;
}
static __device__ __forceinline__ void unpk2(unsigned long long v, float& lo, float& hi) {
    asm("mov.b64 {%0, %1}, %2;" : "=f"(lo), "=f"(hi) : "l"(v));
}

__global__ __launch_bounds__(THREADS) void chamfer_kernel(
    const float* __restrict__ pred,
    const float* __restrict__ targ,
    float* __restrict__ out)
{
    __shared__ ulonglong2 sm[2 * TGROUPS];   // {x0x1,y0y1},{z0z1,w0w1} per group
    __shared__ float warpsums[THREADS / 32];
    __shared__ unsigned int s_done;

    const int bx     = blockIdx.x;
    const int combo  = bx / (SRCSLICES * TCHUNKS);            // 0..15
    const int sslice = (bx / TCHUNKS) % SRCSLICES;            // 0..3
    const int tchunk = bx % TCHUNKS;                          // 0..7
    const int dir    = combo & 1;
    const int b      = combo >> 1;
    const float* __restrict__ sp = (dir == 0 ? pred : targ) + (size_t)b * NPTS * 3;
    const float* __restrict__ tp = (dir == 0 ? targ : pred) + (size_t)b * NPTS * 3;

    // Stage this block's 512-target chunk as packed pair-groups (x,y,z,|t|^2)
    const float* tc = tp + (size_t)tchunk * TCHUNK * 3;
    #pragma unroll
    for (int g = threadIdx.x; g < TGROUPS; g += THREADS) {
        const float* t = tc + 6 * g;
        float x0 = t[0], y0 = t[1], z0 = t[2];
        float x1 = t[3], y1 = t[4], z1 = t[5];
        float w0 = fmaf(x0, x0, fmaf(y0, y0, z0 * z0));
        float w1 = fmaf(x1, x1, fmaf(y1, y1, z1 * z1));
        sm[2 * g]     = make_ulonglong2(pk2(x0, x1), pk2(y0, y1));
        sm[2 * g + 1] = make_ulonglong2(pk2(z0, z1), pk2(w0, w1));
    }

    // This thread's PPT source points
    unsigned long long mx[PPT], my[PPT], mz[PPT];
    float p2[PPT];
    #pragma unroll
    for (int p = 0; p < PPT; p++) {
        const int i = sslice * (THREADS * PPT) + p * THREADS + threadIdx.x;
        float px = sp[3 * i + 0];
        float py = sp[3 * i + 1];
        float pz = sp[3 * i + 2];
        mx[p] = pk2(-2.0f * px, -2.0f * px);
        my[p] = pk2(-2.0f * py, -2.0f * py);
        mz[p] = pk2(-2.0f * pz, -2.0f * pz);
        p2[p] = fmaf(px, px, fmaf(py, py, pz * pz));
    }

    __syncthreads();

    float best0[PPT], best1[PPT];
    #pragma unroll
    for (int p = 0; p < PPT; p++) { best0[p] = INFINITY; best1[p] = INFINITY; }

    #pragma unroll 2
    for (int g = 0; g < TGROUPS; g++) {
        const ulonglong2 A = sm[2 * g];        // {x0x1, y0y1}
        const ulonglong2 C = sm[2 * g + 1];    // {z0z1, w0w1}
        #pragma unroll
        for (int p = 0; p < PPT; p++) {
            unsigned long long v = fma2(mz[p], C.x, C.y);
            v = fma2(my[p], A.y, v);
            v = fma2(mx[p], A.x, v);
            float vlo, vhi;
            unpk2(v, vlo, vhi);
            best0[p] = fminf(best0[p], vlo);
            best1[p] = fminf(best1[p], vhi);
        }
    }

    // Publish partial min d^2 via atomicMax on inverted bits
    #pragma unroll
    for (int p = 0; p < PPT; p++) {
        const int i = sslice * (THREADS * PPT) + p * THREADS + threadIdx.x;
        float d2 = fmaxf(fminf(best0[p], best1[p]) + p2[p], 0.0f);
        atomicMax(&g_keybuf[combo * NPTS + i], ~__float_as_uint(d2));
    }

    // Ticket: last block to finish does the reduction + reset
    __threadfence();
    if (threadIdx.x == 0) s_done = atomicAdd(&g_tick, 1u);
    __syncthreads();

    if (s_done == NBLOCKS - 1) {
        const int tid = threadIdx.x;
        float s = 0.0f;
        const uint4* buf = (const uint4*)g_keybuf;
        #pragma unroll 8
        for (int k = 0; k < NMIN / 4 / THREADS; k++) {   // 128 iterations
            uint4 v = __ldcg(&buf[k * THREADS + tid]);
            s += sqrtf(__uint_as_float(~v.x)) + sqrtf(__uint_as_float(~v.y))
               + sqrtf(__uint_as_float(~v.z)) + sqrtf(__uint_as_float(~v.w));
        }
        #pragma unroll
        for (int o = 16; o > 0; o >>= 1)
            s += __shfl_xor_sync(0xFFFFFFFFu, s, o);
        const int lane = tid & 31, wid = tid >> 5;
        if (lane == 0) warpsums[wid] = s;
        __syncthreads();
        if (tid == 0) {
            float v = warpsums[0] + warpsums[1] + warpsums[2] + warpsums[3];
            out[0] = (float)((double)v / ((double)BATCH * (double)NPTS));
        }
        // Reset buffer + tick for next graph replay
        uint4* wbuf = (uint4*)g_keybuf;
        const uint4 z = make_uint4(0u, 0u, 0u, 0u);
        #pragma unroll 8
        for (int k = 0; k < NMIN / 4 / THREADS; k++)
            wbuf[k * THREADS + tid] = z;
        __threadfence();
        __syncthreads();
        if (tid == 0) g_tick = 0;
    }
}

extern "C" void kernel_launch(void* const* d_in, const int* in_sizes, int n_in,
                              void* d_out, int out_size) {
    const float* pred = (const float*)d_in[0];
    const float* targ = (const float*)d_in[1];
    float* out = (float*)d_out;

    chamfer_kernel<<<NBLOCKS, THREADS>>>(pred, targ, out);
}